// round 2
// baseline (speedup 1.0000x reference)
#include <cuda_runtime.h>
#include <cuda_bf16.h>
#include <math.h>

#define TOKENS  16384
#define D_IN    2048
#define D_HID   1024
#define NEXP    64
#define TOPK    8

// Scratch for the hidden activations (64 MiB). __device__ global: allowed.
__device__ float g_h[(size_t)TOKENS * D_HID];

// ---------------------------------------------------------------------------
// Kernel 1: h = leaky_relu(x @ W1^T + b1)
//   x  [TOKENS, D_IN]  row-major
//   W1 [D_HID,  D_IN]  row-major  (both K-major -> NT GEMM)
// 128x128 block tile, BK=32, 8x8 per-thread tile, 256 threads.
// ---------------------------------------------------------------------------
#define BM 128
#define BN 128
#define BK 32

__global__ __launch_bounds__(256, 2)
void gemm1_kernel(const float* __restrict__ X,
                  const float* __restrict__ W1,
                  const float* __restrict__ b1)
{
    __shared__ float As[BK][BM + 4];   // [k][m]
    __shared__ float Bs[BK][BN + 4];   // [k][n]

    const int tid = threadIdx.x;
    const int tx  = tid & 15;          // 0..15 -> n quad
    const int ty  = tid >> 4;          // 0..15 -> m quad
    const int m0  = blockIdx.y * BM;
    const int n0  = blockIdx.x * BN;

    // global-load mapping: 8 float4 per row of 32 k-floats, 32 rows per pass
    const int lrow = tid >> 3;          // 0..31
    const int lcol = (tid & 7) * 4;     // 0,4,...,28

    float acc[8][8];
#pragma unroll
    for (int i = 0; i < 8; i++)
#pragma unroll
        for (int j = 0; j < 8; j++) acc[i][j] = 0.0f;

    for (int kt = 0; kt < D_IN; kt += BK) {
#pragma unroll
        for (int p = 0; p < 4; p++) {
            const int row = lrow + p * 32;
            float4 a = *(const float4*)(X  + (size_t)(m0 + row) * D_IN + kt + lcol);
            As[lcol + 0][row] = a.x;
            As[lcol + 1][row] = a.y;
            As[lcol + 2][row] = a.z;
            As[lcol + 3][row] = a.w;
            float4 b = *(const float4*)(W1 + (size_t)(n0 + row) * D_IN + kt + lcol);
            Bs[lcol + 0][row] = b.x;
            Bs[lcol + 1][row] = b.y;
            Bs[lcol + 2][row] = b.z;
            Bs[lcol + 3][row] = b.w;
        }
        __syncthreads();

#pragma unroll 4
        for (int k = 0; k < BK; k++) {
            float af[8], bf[8];
            *(float4*)(af + 0) = *(const float4*)&As[k][ty * 8 + 0];
            *(float4*)(af + 4) = *(const float4*)&As[k][ty * 8 + 4];
            *(float4*)(bf + 0) = *(const float4*)&Bs[k][tx * 8 + 0];
            *(float4*)(bf + 4) = *(const float4*)&Bs[k][tx * 8 + 4];
#pragma unroll
            for (int i = 0; i < 8; i++)
#pragma unroll
                for (int j = 0; j < 8; j++)
                    acc[i][j] = fmaf(af[i], bf[j], acc[i][j]);
        }
        __syncthreads();
    }

    // epilogue: +bias, LeakyReLU, store
    float bias[8];
#pragma unroll
    for (int j = 0; j < 8; j++) bias[j] = b1[n0 + tx * 8 + j];

#pragma unroll
    for (int i = 0; i < 8; i++) {
        const int m = m0 + ty * 8 + i;
        float v[8];
#pragma unroll
        for (int j = 0; j < 8; j++) {
            float t = acc[i][j] + bias[j];
            v[j] = (t >= 0.0f) ? t : 0.01f * t;
        }
        float* dst = g_h + (size_t)m * D_HID + n0 + tx * 8;
        *(float4*)(dst + 0) = make_float4(v[0], v[1], v[2], v[3]);
        *(float4*)(dst + 4) = make_float4(v[4], v[5], v[6], v[7]);
    }
}

// ---------------------------------------------------------------------------
// Kernel 2: logits = h @ W2^T + b2 ; top-8 ; softmax ; write probs + indices
// Block = 64 tokens, 256 threads. K chunked at 64.
// ---------------------------------------------------------------------------
#define TT 64
#define KC 64
#define LSTR (TT + 4)   // 68, keeps float4 alignment

__global__ __launch_bounds__(256, 1)
void router_kernel(const float* __restrict__ W2,
                   const float* __restrict__ b2,
                   float* __restrict__ out,
                   int write_indices)
{
    __shared__ float smem[2 * KC * LSTR];
    float (*Hs)[LSTR] = (float(*)[LSTR])(smem);                 // [k][token]
    float (*Ws)[LSTR] = (float(*)[LSTR])(smem + KC * LSTR);     // [k][expert]
    float* Lg = smem;   // reused after GEMM: logits [token][LSTR]

    const int tid  = threadIdx.x;
    const int tx   = tid & 15;   // expert quad
    const int ty   = tid >> 4;   // token quad
    const int t0   = blockIdx.x * TT;

    const int lrow = tid >> 4;        // 0..15
    const int lcol = (tid & 15) * 4;  // 0,4,...,60

    float acc[4][4];
#pragma unroll
    for (int i = 0; i < 4; i++)
#pragma unroll
        for (int j = 0; j < 4; j++) acc[i][j] = 0.0f;

    for (int kc = 0; kc < D_HID; kc += KC) {
#pragma unroll
        for (int p = 0; p < 4; p++) {
            const int row = lrow + p * 16;
            float4 a = *(const float4*)(g_h + (size_t)(t0 + row) * D_HID + kc + lcol);
            Hs[lcol + 0][row] = a.x;
            Hs[lcol + 1][row] = a.y;
            Hs[lcol + 2][row] = a.z;
            Hs[lcol + 3][row] = a.w;
            float4 b = *(const float4*)(W2 + (size_t)row * D_HID + kc + lcol);
            Ws[lcol + 0][row] = b.x;
            Ws[lcol + 1][row] = b.y;
            Ws[lcol + 2][row] = b.z;
            Ws[lcol + 3][row] = b.w;
        }
        __syncthreads();

#pragma unroll 8
        for (int k = 0; k < KC; k++) {
            float4 a = *(const float4*)&Hs[k][ty * 4];
            float4 b = *(const float4*)&Ws[k][tx * 4];
            float af[4] = {a.x, a.y, a.z, a.w};
            float bf[4] = {b.x, b.y, b.z, b.w};
#pragma unroll
            for (int i = 0; i < 4; i++)
#pragma unroll
                for (int j = 0; j < 4; j++)
                    acc[i][j] = fmaf(af[i], bf[j], acc[i][j]);
        }
        __syncthreads();
    }

    // bias + write logits into reused smem
    float bb[4];
#pragma unroll
    for (int j = 0; j < 4; j++) bb[j] = b2[tx * 4 + j];

#pragma unroll
    for (int i = 0; i < 4; i++) {
        float4 v = make_float4(acc[i][0] + bb[0], acc[i][1] + bb[1],
                               acc[i][2] + bb[2], acc[i][3] + bb[3]);
        *(float4*)&Lg[(ty * 4 + i) * LSTR + tx * 4] = v;
    }
    __syncthreads();

    // top-8 + softmax: 8 warps, 8 tokens each
    const int warp = tid >> 5;
    const int lane = tid & 31;
    const float NEG = -3.402823466e38f;

    for (int s = 0; s < 8; s++) {
        const int lt = warp * 8 + s;
        float v0 = Lg[lt * LSTR + lane];
        float v1 = Lg[lt * LSTR + 32 + lane];
        const int i0 = lane;
        const int i1 = lane + 32;

        float pv[TOPK];
        int   pi[TOPK];
#pragma unroll
        for (int r = 0; r < TOPK; r++) {
            float bv; int bi;
            if (v0 >= v1) { bv = v0; bi = i0; } else { bv = v1; bi = i1; }
#pragma unroll
            for (int off = 16; off >= 1; off >>= 1) {
                float ov = __shfl_xor_sync(0xffffffffu, bv, off);
                int   oi = __shfl_xor_sync(0xffffffffu, bi, off);
                if (ov > bv || (ov == bv && oi < bi)) { bv = ov; bi = oi; }
            }
            pv[r] = bv; pi[r] = bi;
            if (bi == i0)       v0 = NEG;
            else if (bi == i1)  v1 = NEG;
        }

        if (lane == 0) {
            const float mx = pv[0];
            float e[TOPK], sum = 0.0f;
#pragma unroll
            for (int r = 0; r < TOPK; r++) { e[r] = expf(pv[r] - mx); sum += e[r]; }
            const float inv = 1.0f / sum;
            const int gt = t0 + lt;
#pragma unroll
            for (int r = 0; r < TOPK; r++)
                out[(size_t)gt * TOPK + r] = e[r] * inv;
            if (write_indices) {
#pragma unroll
                for (int r = 0; r < TOPK; r++)
                    out[(size_t)TOKENS * TOPK + (size_t)gt * TOPK + r] = (float)pi[r];
            }
        }
    }
}

// ---------------------------------------------------------------------------
extern "C" void kernel_launch(void* const* d_in, const int* in_sizes, int n_in,
                              void* d_out, int out_size)
{
    const float* X  = (const float*)d_in[0];
    const float* W1 = (const float*)d_in[1];
    const float* b1 = (const float*)d_in[2];
    const float* W2 = (const float*)d_in[3];
    const float* b2 = (const float*)d_in[4];
    float* out = (float*)d_out;

    const int write_indices = (out_size >= 2 * TOKENS * TOPK) ? 1 : 0;

    dim3 g1(D_HID / BN, TOKENS / BM);
    gemm1_kernel<<<g1, 256>>>(X, W1, b1);
    router_kernel<<<TOKENS / TT, 256>>>(W2, b2, out, write_indices);
}

// round 4
// speedup vs baseline: 1.2321x; 1.2321x over previous
#include <cuda_runtime.h>
#include <cuda_bf16.h>
#include <math.h>
#include <stdint.h>

#define TOKENS  16384
#define D_IN    2048
#define D_HID   1024
#define NEXP    64
#define TOPK    8

// ---------------------------------------------------------------------------
// Scratch (__device__ globals: allowed)
// ---------------------------------------------------------------------------
__device__ float g_h[(size_t)TOKENS * D_HID];                 // 64 MiB
__device__ __nv_bfloat16 g_xh[(size_t)TOKENS * D_IN];
__device__ __nv_bfloat16 g_xm[(size_t)TOKENS * D_IN];
__device__ __nv_bfloat16 g_xl[(size_t)TOKENS * D_IN];
__device__ __nv_bfloat16 g_wh[(size_t)D_HID * D_IN];
__device__ __nv_bfloat16 g_wm[(size_t)D_HID * D_IN];
__device__ __nv_bfloat16 g_wl[(size_t)D_HID * D_IN];

// ---------------------------------------------------------------------------
// Helpers
// ---------------------------------------------------------------------------
__device__ __forceinline__ uint32_t smem_to_u32(const void* smem_ptr) {
    uint32_t addr;
    asm("{ .reg .u64 tmp; cvta.to.shared.u64 tmp, %1; cvt.u32.u64 %0, tmp; }"
        : "=r"(addr) : "l"(smem_ptr));
    return addr;
}

__device__ __forceinline__ void cp16(uint32_t s, const void* g) {
    asm volatile("cp.async.cg.shared.global [%0], [%1], 16;" :: "r"(s), "l"(g));
}
#define CP_COMMIT()  asm volatile("cp.async.commit_group;" ::: "memory")
#define CP_WAIT1()   asm volatile("cp.async.wait_group 1;" ::: "memory")
#define CP_WAIT0()   asm volatile("cp.async.wait_group 0;" ::: "memory")

__device__ __forceinline__ void ldsm_x4(uint32_t* r, uint32_t addr) {
    asm volatile("ldmatrix.sync.aligned.m8n8.x4.shared.b16 {%0,%1,%2,%3}, [%4];"
        : "=r"(r[0]), "=r"(r[1]), "=r"(r[2]), "=r"(r[3]) : "r"(addr));
}
__device__ __forceinline__ void ldsm_x2(uint32_t* r, uint32_t addr) {
    asm volatile("ldmatrix.sync.aligned.m8n8.x2.shared.b16 {%0,%1}, [%2];"
        : "=r"(r[0]), "=r"(r[1]) : "r"(addr));
}

__device__ __forceinline__ void mma16816(float* c, const uint32_t* a, const uint32_t* b) {
    asm volatile(
        "mma.sync.aligned.m16n8k16.row.col.f32.bf16.bf16.f32 "
        "{%0,%1,%2,%3}, {%4,%5,%6,%7}, {%8,%9}, {%0,%1,%2,%3};"
        : "+f"(c[0]), "+f"(c[1]), "+f"(c[2]), "+f"(c[3])
        : "r"(a[0]), "r"(a[1]), "r"(a[2]), "r"(a[3]), "r"(b[0]), "r"(b[1]));
}

__device__ __forceinline__ uint32_t sw128(uint32_t off) {
    return off ^ ((off >> 3) & 0x70);
}

// ---------------------------------------------------------------------------
// Kernel S: 3-way bf16 split (a = h + m + l, residual ~2^-27)
// ---------------------------------------------------------------------------
__global__ void split_kernel(const float* __restrict__ src, int n4, int which)
{
    __nv_bfloat16 *dh, *dm, *dl;
    if (which == 0) { dh = g_xh; dm = g_xm; dl = g_xl; }
    else            { dh = g_wh; dm = g_wm; dl = g_wl; }

    int i = blockIdx.x * blockDim.x + threadIdx.x;
    const int stride = gridDim.x * blockDim.x;
    for (; i < n4; i += stride) {
        float4 v = ((const float4*)src)[i];
        float a[4] = {v.x, v.y, v.z, v.w};
        __nv_bfloat16 h[4], m[4], l[4];
#pragma unroll
        for (int j = 0; j < 4; j++) {
            h[j] = __float2bfloat16(a[j]);
            float r1 = a[j] - __bfloat162float(h[j]);
            m[j] = __float2bfloat16(r1);
            float r2 = r1 - __bfloat162float(m[j]);
            l[j] = __float2bfloat16(r2);
        }
        __nv_bfloat162* ph = (__nv_bfloat162*)dh;
        __nv_bfloat162* pm = (__nv_bfloat162*)dm;
        __nv_bfloat162* pl = (__nv_bfloat162*)dl;
        ph[2*i]   = __nv_bfloat162(h[0], h[1]);
        ph[2*i+1] = __nv_bfloat162(h[2], h[3]);
        pm[2*i]   = __nv_bfloat162(m[0], m[1]);
        pm[2*i+1] = __nv_bfloat162(m[2], m[3]);
        pl[2*i]   = __nv_bfloat162(l[0], l[1]);
        pl[2*i+1] = __nv_bfloat162(l[2], l[3]);
    }
}

// ---------------------------------------------------------------------------
// Kernel G: h = leaky(x @ W1^T + b1) via mma.sync bf16, 6-product split GEMM
// CTA 128x128, BK=64, double-buffered cp.async SW128 SMEM, 8 warps (2m x 4n),
// warp fragment 64x32, shared fp32 accumulators across all 6 products.
// ---------------------------------------------------------------------------
#define GM 128
#define GN 128
#define GK 64
#define NCHUNK (D_IN / GK)          // 32
#define TILE_B 16384                // 128 rows x 128 bytes (SW128)
#define STAGE_B (6 * TILE_B)        // Ah Am Al Bh Bm Bl
#define SMEM_CTRL 1024
#define SMEM_TOTAL_G (SMEM_CTRL + 2 * STAGE_B)   // 197632

__global__ __launch_bounds__(256, 1)
void gemm1_mma_kernel(const float* __restrict__ b1)
{
    extern __shared__ char smem[];
    const uint32_t sb = smem_to_u32(smem);
    const int tid  = threadIdx.x;
    const int wid  = tid >> 5;
    const int lane = tid & 31;
    const int m0 = blockIdx.y * GM;
    const int n0 = blockIdx.x * GN;

    const int wm0 = (wid & 1) * 64;      // warp m offset in CTA tile
    const int wn0 = (wid >> 1) * 32;     // warp n offset in CTA tile

    // global->smem loader geometry (4 x 16B per thread per 16KB tile)
    size_t   goff[4];
    uint32_t soff[4];
#pragma unroll
    for (int p = 0; p < 4; p++) {
        int u = tid + p * 256;
        int row = u >> 3, c16 = u & 7;
        goff[p] = (size_t)row * D_IN + c16 * 8;
        soff[p] = sw128(row * 128 + c16 * 16);
    }

    const __nv_bfloat16* Ab[3] = { g_xh + (size_t)m0 * D_IN,
                                   g_xm + (size_t)m0 * D_IN,
                                   g_xl + (size_t)m0 * D_IN };
    const __nv_bfloat16* Bb[3] = { g_wh + (size_t)n0 * D_IN,
                                   g_wm + (size_t)n0 * D_IN,
                                   g_wl + (size_t)n0 * D_IN };

    auto load_chunk = [&](int chunk, int buf) {
        const int kt = chunk * GK;
        const uint32_t stg = sb + SMEM_CTRL + buf * STAGE_B;
#pragma unroll
        for (int t = 0; t < 6; t++) {
            const __nv_bfloat16* base = (t < 3) ? Ab[t] : Bb[t - 3];
            const uint32_t sbase = stg + t * TILE_B;
#pragma unroll
            for (int p = 0; p < 4; p++)
                cp16(sbase + soff[p], base + goff[p] + kt);
        }
        CP_COMMIT();
    };

    // ldmatrix per-lane offsets (within a tile)
    // A (x4): row = wm0 + mi*16 + (lane&15), kbyte = (ks*16 + (lane>>4)*8)*2
    const uint32_t a_row = wm0 + (lane & 15);
    const uint32_t a_kb  = (lane >> 4) * 16;
    // B (x2): row = wn0 + ni*8 + (l&7), kbyte = (ks*16 + ((l>>3)&1)*8)*2
    const uint32_t b_row = wn0 + (lane & 7);
    const uint32_t b_kb  = ((lane >> 3) & 1) * 16;

    // product schedule: hh, hm, mh, hl, lh, mm (A idx, B idx)
    const int AI[6] = {0, 0, 1, 0, 2, 1};
    const int BI[6] = {0, 1, 0, 2, 0, 1};

    float acc[4][4][4];
#pragma unroll
    for (int mi = 0; mi < 4; mi++)
#pragma unroll
        for (int ni = 0; ni < 4; ni++)
#pragma unroll
            for (int e = 0; e < 4; e++) acc[mi][ni][e] = 0.0f;

    load_chunk(0, 0);
    load_chunk(1, 1);

    for (int i = 0; i < NCHUNK; i++) {
        if (i + 2 < NCHUNK) CP_WAIT1(); else CP_WAIT0();
        __syncthreads();

        const uint32_t stg = sb + SMEM_CTRL + (i & 1) * STAGE_B;
#pragma unroll
        for (int c = 0; c < 6; c++) {
            const uint32_t abase = stg + AI[c] * TILE_B;
            const uint32_t bbase = stg + (3 + BI[c]) * TILE_B;
#pragma unroll
            for (int ks = 0; ks < 4; ks++) {
                uint32_t af[4][4];
#pragma unroll
                for (int mi = 0; mi < 4; mi++) {
                    uint32_t off = (a_row + mi * 16) * 128 + ks * 32 + a_kb;
                    ldsm_x4(af[mi], abase + sw128(off));
                }
                uint32_t bf[4][2];
#pragma unroll
                for (int ni = 0; ni < 4; ni++) {
                    uint32_t off = (b_row + ni * 8) * 128 + ks * 32 + b_kb;
                    ldsm_x2(bf[ni], bbase + sw128(off));
                }
#pragma unroll
                for (int mi = 0; mi < 4; mi++)
#pragma unroll
                    for (int ni = 0; ni < 4; ni++)
                        mma16816(acc[mi][ni], af[mi], bf[ni]);
            }
        }
        __syncthreads();
        if (i + 2 < NCHUNK) load_chunk(i + 2, i & 1);
    }

    // epilogue: +bias, LeakyReLU, store fragments
    float2 bv[4];
#pragma unroll
    for (int ni = 0; ni < 4; ni++) {
        int col = n0 + wn0 + ni * 8 + (lane & 3) * 2;
        bv[ni] = make_float2(b1[col], b1[col + 1]);
    }

#pragma unroll
    for (int mi = 0; mi < 4; mi++) {
        const int r0 = m0 + wm0 + mi * 16 + (lane >> 2);
#pragma unroll
        for (int ni = 0; ni < 4; ni++) {
            const int col = n0 + wn0 + ni * 8 + (lane & 3) * 2;
            float t0 = acc[mi][ni][0] + bv[ni].x;
            float t1 = acc[mi][ni][1] + bv[ni].y;
            float t2 = acc[mi][ni][2] + bv[ni].x;
            float t3 = acc[mi][ni][3] + bv[ni].y;
            t0 = (t0 >= 0.f) ? t0 : 0.01f * t0;
            t1 = (t1 >= 0.f) ? t1 : 0.01f * t1;
            t2 = (t2 >= 0.f) ? t2 : 0.01f * t2;
            t3 = (t3 >= 0.f) ? t3 : 0.01f * t3;
            *(float2*)(g_h + (size_t)r0 * D_HID + col)       = make_float2(t0, t1);
            *(float2*)(g_h + (size_t)(r0 + 8) * D_HID + col) = make_float2(t2, t3);
        }
    }
}

// ---------------------------------------------------------------------------
// Kernel R: logits = h @ W2^T + b2 ; top-8 ; softmax  (unchanged)
// ---------------------------------------------------------------------------
#define TT 64
#define KC 64
#define LSTR (TT + 4)

__global__ __launch_bounds__(256, 1)
void router_kernel(const float* __restrict__ W2,
                   const float* __restrict__ b2,
                   float* __restrict__ out,
                   int write_indices)
{
    __shared__ float smem[2 * KC * LSTR];
    float (*Hs)[LSTR] = (float(*)[LSTR])(smem);
    float (*Ws)[LSTR] = (float(*)[LSTR])(smem + KC * LSTR);
    float* Lg = smem;

    const int tid  = threadIdx.x;
    const int tx   = tid & 15;
    const int ty   = tid >> 4;
    const int t0   = blockIdx.x * TT;

    const int lrow = tid >> 4;
    const int lcol = (tid & 15) * 4;

    float acc[4][4];
#pragma unroll
    for (int i = 0; i < 4; i++)
#pragma unroll
        for (int j = 0; j < 4; j++) acc[i][j] = 0.0f;

    for (int kc = 0; kc < D_HID; kc += KC) {
#pragma unroll
        for (int p = 0; p < 4; p++) {
            const int row = lrow + p * 16;
            float4 a = *(const float4*)(g_h + (size_t)(t0 + row) * D_HID + kc + lcol);
            Hs[lcol + 0][row] = a.x;
            Hs[lcol + 1][row] = a.y;
            Hs[lcol + 2][row] = a.z;
            Hs[lcol + 3][row] = a.w;
            float4 b = *(const float4*)(W2 + (size_t)row * D_HID + kc + lcol);
            Ws[lcol + 0][row] = b.x;
            Ws[lcol + 1][row] = b.y;
            Ws[lcol + 2][row] = b.z;
            Ws[lcol + 3][row] = b.w;
        }
        __syncthreads();

#pragma unroll 8
        for (int k = 0; k < KC; k++) {
            float4 a = *(const float4*)&Hs[k][ty * 4];
            float4 b = *(const float4*)&Ws[k][tx * 4];
            float af[4] = {a.x, a.y, a.z, a.w};
            float bf[4] = {b.x, b.y, b.z, b.w};
#pragma unroll
            for (int i = 0; i < 4; i++)
#pragma unroll
                for (int j = 0; j < 4; j++)
                    acc[i][j] = fmaf(af[i], bf[j], acc[i][j]);
        }
        __syncthreads();
    }

    float bb[4];
#pragma unroll
    for (int j = 0; j < 4; j++) bb[j] = b2[tx * 4 + j];

#pragma unroll
    for (int i = 0; i < 4; i++) {
        float4 v = make_float4(acc[i][0] + bb[0], acc[i][1] + bb[1],
                               acc[i][2] + bb[2], acc[i][3] + bb[3]);
        *(float4*)&Lg[(ty * 4 + i) * LSTR + tx * 4] = v;
    }
    __syncthreads();

    const int warp = tid >> 5;
    const int lane = tid & 31;
    const float NEG = -3.402823466e38f;

    for (int s = 0; s < 8; s++) {
        const int lt = warp * 8 + s;
        float v0 = Lg[lt * LSTR + lane];
        float v1 = Lg[lt * LSTR + 32 + lane];
        const int i0 = lane;
        const int i1 = lane + 32;

        float pv[TOPK];
        int   pi[TOPK];
#pragma unroll
        for (int r = 0; r < TOPK; r++) {
            float bv; int bi;
            if (v0 >= v1) { bv = v0; bi = i0; } else { bv = v1; bi = i1; }
#pragma unroll
            for (int off = 16; off >= 1; off >>= 1) {
                float ov = __shfl_xor_sync(0xffffffffu, bv, off);
                int   oi = __shfl_xor_sync(0xffffffffu, bi, off);
                if (ov > bv || (ov == bv && oi < bi)) { bv = ov; bi = oi; }
            }
            pv[r] = bv; pi[r] = bi;
            if (bi == i0)       v0 = NEG;
            else if (bi == i1)  v1 = NEG;
        }

        if (lane == 0) {
            const float mx = pv[0];
            float e[TOPK], sum = 0.0f;
#pragma unroll
            for (int r = 0; r < TOPK; r++) { e[r] = expf(pv[r] - mx); sum += e[r]; }
            const float inv = 1.0f / sum;
            const int gt = t0 + lt;
#pragma unroll
            for (int r = 0; r < TOPK; r++)
                out[(size_t)gt * TOPK + r] = e[r] * inv;
            if (write_indices) {
#pragma unroll
                for (int r = 0; r < TOPK; r++)
                    out[(size_t)TOKENS * TOPK + (size_t)gt * TOPK + r] = (float)pi[r];
            }
        }
    }
}

// ---------------------------------------------------------------------------
extern "C" void kernel_launch(void* const* d_in, const int* in_sizes, int n_in,
                              void* d_out, int out_size)
{
    const float* X  = (const float*)d_in[0];
    const float* W1 = (const float*)d_in[1];
    const float* b1 = (const float*)d_in[2];
    const float* W2 = (const float*)d_in[3];
    const float* b2 = (const float*)d_in[4];
    float* out = (float*)d_out;

    const int write_indices = (out_size >= 2 * TOKENS * TOPK) ? 1 : 0;

    static int smem_set = 0;
    if (!smem_set) {
        cudaFuncSetAttribute(gemm1_mma_kernel,
                             cudaFuncAttributeMaxDynamicSharedMemorySize, SMEM_TOTAL_G);
        smem_set = 1;
    }

    split_kernel<<<4096, 256>>>(X,  (TOKENS * D_IN) / 4, 0);
    split_kernel<<<2048, 256>>>(W1, (D_HID * D_IN) / 4, 1);

    dim3 gg(D_HID / GN, TOKENS / GM);
    gemm1_mma_kernel<<<gg, 256, SMEM_TOTAL_G>>>(b1);

    router_kernel<<<TOKENS / TT, 256>>>(W2, b2, out, write_indices);
}